// round 1
// baseline (speedup 1.0000x reference)
#include <cuda_runtime.h>
#include <math.h>

#define N_IMG 8
#define CH    100
#define OD    32
#define NC    20
#define HH    256
#define WW    256
#define PIX   (HH*WW)      // 65536

// ---------------- scratch (static device globals; no allocations) ----------------
__device__ float g_xs  [N_IMG*3*PIX];        // downsampled input  [8,3,256,256]
__device__ float g_fs  [N_IMG*NC*256];       // small features     [8,20,16,16]
__device__ float g_fup [N_IMG*NC*PIX];       // upsampled features [8,20,256,256]
__device__ float g_y1  [N_IMG*CH*PIX];       // conv1 out
__device__ float g_y2  [N_IMG*CH*PIX];       // conv2 out
__device__ int   g_lab [N_IMG*PIX];          // argmax labels
__device__ float g_sums[N_IMG*OD*NC];
__device__ float g_cnt [N_IMG*OD];
__device__ float g_means[N_IMG*OD*NC];
// bn params: [0,100)=s1 [100,200)=t1 [200,300)=s2 [300,400)=t2 [400,432)=s3 [432,464)=t3
__device__ float g_bnp[464];

// ---------------- bn prep ----------------
__global__ void k_bnprep(const float* g1, const float* be1, const float* m1, const float* v1,
                         const float* g2, const float* be2, const float* m2, const float* v2,
                         const float* g3, const float* be3, const float* m3, const float* v3) {
    int t = threadIdx.x;
    if (t < 100) {
        float s = g1[t] / sqrtf(v1[t] + 1e-5f);
        g_bnp[t] = s; g_bnp[100 + t] = be1[t] - m1[t] * s;
    } else if (t < 200) {
        int i = t - 100;
        float s = g2[i] / sqrtf(v2[i] + 1e-5f);
        g_bnp[200 + i] = s; g_bnp[300 + i] = be2[i] - m2[i] * s;
    } else if (t < 232) {
        int i = t - 200;
        float s = g3[i] / sqrtf(v3[i] + 1e-5f);
        g_bnp[400 + i] = s; g_bnp[432 + i] = be3[i] - m3[i] * s;
    }
}

// ---------------- classifier 1x1 conv + spatial max ----------------
// grid: 160 blocks (n*20+oc), 256 threads (one per spatial pos of 16x16)
__global__ void k_classifier(const float* __restrict__ x4, const float* __restrict__ Wc,
                             float* __restrict__ cls_out) {
    int b = blockIdx.x;
    int n = b / NC, oc = b % NC;
    __shared__ float wsh[512];
    __shared__ float red[256];
    int t = threadIdx.x;
    wsh[t]       = Wc[oc * 512 + t];
    wsh[t + 256] = Wc[oc * 512 + t + 256];
    __syncthreads();
    const float* xp = x4 + (long)n * 512 * 256;
    float acc = 0.f;
    #pragma unroll 8
    for (int c = 0; c < 512; c++) acc = fmaf(xp[c * 256 + t], wsh[c], acc);
    g_fs[(n * NC + oc) * 256 + t] = acc;
    red[t] = acc; __syncthreads();
    for (int s = 128; s > 0; s >>= 1) {
        if (t < s) red[t] = fmaxf(red[t], red[t + s]);
        __syncthreads();
    }
    if (t == 0) cls_out[n * NC + oc] = red[0];
}

// ---------------- bilinear upsample 16x16 -> 256x256 (half-pixel, clamp) ----------------
__global__ void k_up() {
    int idx = blockIdx.x * 256 + threadIdx.x;       // < 8*20*65536
    int x = idx & 255;
    int y = (idx >> 8) & 255;
    int nc = idx >> 16;
    float sy = (y + 0.5f) * 0.0625f - 0.5f;
    float sx = (x + 0.5f) * 0.0625f - 0.5f;
    float fy0 = floorf(sy), fx0 = floorf(sx);
    float fy = sy - fy0, fx = sx - fx0;
    int y0 = max((int)fy0, 0), y1 = min((int)fy0 + 1, 15);
    int x0 = max((int)fx0, 0), x1 = min((int)fx0 + 1, 15);
    const float* fs = g_fs + nc * 256;
    float v00 = fs[y0 * 16 + x0], v01 = fs[y0 * 16 + x1];
    float v10 = fs[y1 * 16 + x0], v11 = fs[y1 * 16 + x1];
    float v = (v00 * (1.f - fx) + v01 * fx) * (1.f - fy) + (v10 * (1.f - fx) + v11 * fx) * fy;
    g_fup[idx] = v;
}

// ---------------- antialiased bilinear downsample 512 -> 256 ----------------
// per-axis taps {2d-1..2d+2} weights {1,3,3,1}, oob dropped + renormalized (jax antialias=True)
__device__ __forceinline__ float d_taps(int d, int* ix, float* wv) {
    float s = 0.f;
    #pragma unroll
    for (int i = 0; i < 4; i++) {
        int p = 2 * d - 1 + i;
        float w = (i == 0 || i == 3) ? 1.f : 3.f;
        if (p < 0 || p >= 512) { w = 0.f; p = p < 0 ? 0 : 511; }
        ix[i] = p; wv[i] = w; s += w;
    }
    return s;
}

__global__ void k_down(const float* __restrict__ x) {
    int idx = blockIdx.x * 256 + threadIdx.x;       // < 8*3*65536
    int xo = idx & 255;
    int yo = (idx >> 8) & 255;
    int nc = idx >> 16;                              // n*3 + c
    int iy[4], ixs[4];
    float wy[4], wx[4];
    float ny = d_taps(yo, iy, wy);
    float nx = d_taps(xo, ixs, wx);
    const float* xp = x + (long)nc * 512 * 512;
    float acc = 0.f;
    #pragma unroll
    for (int i = 0; i < 4; i++) {
        const float* row = xp + iy[i] * 512;
        float r = wx[0]*row[ixs[0]] + wx[1]*row[ixs[1]] + wx[2]*row[ixs[2]] + wx[3]*row[ixs[3]];
        acc += wy[i] * r;
    }
    g_xs[idx] = acc / (ny * nx);
}

// ---------------- conv1: 3x3, 3->100, +bias, relu, bn ----------------
// grid: (256 pixblocks, 25 oc-groups of 4, 8 n), 256 threads
__global__ void k_conv1(const float* __restrict__ W1, const float* __restrict__ b1) {
    __shared__ float ws[4 * 27];
    __shared__ float bs[4], ss[4], ts[4];
    int t = threadIdx.x;
    int n = blockIdx.z, ocg = blockIdx.y;
    if (t < 108) ws[t] = W1[ocg * 108 + t];
    if (t < 4) {
        int oc = ocg * 4 + t;
        bs[t] = b1[oc]; ss[t] = g_bnp[oc]; ts[t] = g_bnp[100 + oc];
    }
    __syncthreads();
    int p = blockIdx.x * 256 + t;
    int y = p >> 8, x = p & 255;
    const float* xp = g_xs + n * 3 * PIX;
    float in[27];
    int k = 0;
    #pragma unroll
    for (int c = 0; c < 3; c++)
        #pragma unroll
        for (int dy = -1; dy <= 1; dy++) {
            int yy = y + dy;
            #pragma unroll
            for (int dx = -1; dx <= 1; dx++) {
                int xx = x + dx;
                in[k++] = ((unsigned)yy < 256u && (unsigned)xx < 256u) ? xp[c * PIX + yy * 256 + xx] : 0.f;
            }
        }
    #pragma unroll
    for (int o = 0; o < 4; o++) {
        float a = bs[o];
        #pragma unroll
        for (int j = 0; j < 27; j++) a = fmaf(in[j], ws[o * 27 + j], a);
        a = fmaxf(a, 0.f);
        a = fmaf(a, ss[o], ts[o]);
        g_y1[((n * CH + ocg * 4 + o) * PIX) + p] = a;
    }
}

// ---------------- conv2: 3x3, 100->100, +bias, relu, bn (the hot kernel) ----------------
// 128 threads, tile = 20 oc x 16x16 pixels, each thread 20 oc x 2 pixels
#define OCT 20
__global__ void k_conv2(const float* __restrict__ W2, const float* __restrict__ b2) {
    __shared__ float sIn[2][18 * 18];
    __shared__ float sW[2][OCT * 9];
    int t = threadIdx.x;
    int n = blockIdx.z, ocg = blockIdx.y;
    int tileY = (blockIdx.x >> 4) * 16;
    int tileX = (blockIdx.x & 15) * 16;
    int ty = t >> 3;           // 0..15
    int cx = (t & 7) * 2;      // 0,2,..,14

    float acc[OCT][2];
    #pragma unroll
    for (int o = 0; o < OCT; o++) { acc[o][0] = 0.f; acc[o][1] = 0.f; }

    const float* src = g_y1 + (long)n * CH * PIX;
    const float* wsrc = W2 + ocg * OCT * 900;

    for (int ic0 = 0; ic0 < CH; ic0 += 2) {
        __syncthreads();
        // load 2 input tiles of 18x18 (zero-padded at borders)
        for (int i = t; i < 2 * 324; i += 128) {
            int icc = i / 324, rem = i - icc * 324;
            int r = rem / 18, c = rem - r * 18;
            int yy = tileY - 1 + r, xx = tileX - 1 + c;
            float v = 0.f;
            if ((unsigned)yy < 256u && (unsigned)xx < 256u)
                v = src[(ic0 + icc) * PIX + yy * 256 + xx];
            sIn[icc][rem] = v;
        }
        // load weights for 2 ic x 20 oc x 9
        for (int i = t; i < 2 * OCT * 9; i += 128) {
            int icc = i / (OCT * 9), rem = i - icc * (OCT * 9);
            int o = rem / 9, kk = rem - o * 9;
            sW[icc][rem] = wsrc[o * 900 + (ic0 + icc) * 9 + kk];
        }
        __syncthreads();

        #pragma unroll
        for (int icc = 0; icc < 2; icc++) {
            float a[3][4];
            const float* ip = &sIn[icc][ty * 18 + cx];
            #pragma unroll
            for (int r = 0; r < 3; r++)
                #pragma unroll
                for (int c = 0; c < 4; c++) a[r][c] = ip[r * 18 + c];
            const float* wp = sW[icc];
            #pragma unroll
            for (int o = 0; o < OCT; o++) {
                float w0 = wp[o*9+0], w1 = wp[o*9+1], w2 = wp[o*9+2];
                float w3 = wp[o*9+3], w4 = wp[o*9+4], w5 = wp[o*9+5];
                float w6 = wp[o*9+6], w7 = wp[o*9+7], w8 = wp[o*9+8];
                acc[o][0] += w0*a[0][0] + w1*a[0][1] + w2*a[0][2]
                           + w3*a[1][0] + w4*a[1][1] + w5*a[1][2]
                           + w6*a[2][0] + w7*a[2][1] + w8*a[2][2];
                acc[o][1] += w0*a[0][1] + w1*a[0][2] + w2*a[0][3]
                           + w3*a[1][1] + w4*a[1][2] + w5*a[1][3]
                           + w6*a[2][1] + w7*a[2][2] + w8*a[2][3];
            }
        }
    }
    // epilogue: bias, relu, bn, store
    int p = (tileY + ty) * 256 + tileX + cx;
    #pragma unroll
    for (int o = 0; o < OCT; o++) {
        int oc = ocg * OCT + o;
        float b = b2[oc], s = g_bnp[200 + oc], sh = g_bnp[300 + oc];
        float v0 = fmaf(fmaxf(acc[o][0] + b, 0.f), s, sh);
        float v1 = fmaf(fmaxf(acc[o][1] + b, 0.f), s, sh);
        float* dst = g_y2 + (long)(n * CH + oc) * PIX + p;
        dst[0] = v0; dst[1] = v1;
    }
}

// ---------------- conv3: 1x1, 100->32, +bias, bn, write mask, argmax ----------------
// grid: (256 pixblocks, 8 n), 256 threads
__global__ void k_conv3(const float* __restrict__ W3, const float* __restrict__ b3,
                        float* __restrict__ out_mask) {
    __shared__ float w3s[100 * 32];     // [c][oc]
    __shared__ float p3[96];
    int t = threadIdx.x, n = blockIdx.y;
    for (int i = t; i < 3200; i += 256) {
        int oc = i & 31, c = i >> 5;
        w3s[i] = W3[oc * 100 + c];
    }
    if (t < 32) { p3[t] = b3[t]; p3[32 + t] = g_bnp[400 + t]; p3[64 + t] = g_bnp[432 + t]; }
    __syncthreads();
    int p = blockIdx.x * 256 + t;
    const float* yp = g_y2 + (long)n * CH * PIX + p;
    float acc[32];
    #pragma unroll
    for (int o = 0; o < 32; o++) acc[o] = 0.f;
    for (int c = 0; c < 100; c++) {
        float v = yp[c * PIX];
        #pragma unroll
        for (int o = 0; o < 32; o++) acc[o] = fmaf(v, w3s[c * 32 + o], acc[o]);
    }
    float best = -INFINITY;
    int bi = 0;
    #pragma unroll
    for (int o = 0; o < 32; o++) {
        float m = fmaf(acc[o] + p3[o], p3[32 + o], p3[64 + o]);
        out_mask[(long)(n * OD + o) * PIX + p] = m;
        if (m > best) { best = m; bi = o; }   // strict > == first-occurrence argmax
    }
    g_lab[n * PIX + p] = bi;
}

// ---------------- segment stats ----------------
__global__ void k_zero() {
    int i = blockIdx.x * 256 + threadIdx.x;
    if (i < N_IMG * OD * NC) g_sums[i] = 0.f;
    if (i < N_IMG * OD) g_cnt[i] = 0.f;
}

// grid: (16 chunks, 8 n), 256 threads; 4096 pixels per block
__global__ void k_segsum() {
    __shared__ float sb[NC * OD];   // [c][label]
    __shared__ float sc[OD];
    int t = threadIdx.x, n = blockIdx.y;
    for (int i = t; i < NC * OD; i += 256) sb[i] = 0.f;
    if (t < OD) sc[t] = 0.f;
    __syncthreads();
    int pbase = blockIdx.x * 4096;
    for (int it = 0; it < 16; it++) {
        int p = pbase + it * 256 + t;
        int l = g_lab[n * PIX + p];
        atomicAdd(&sc[l], 1.f);
        const float* fp = g_fup + (long)n * NC * PIX + p;
        #pragma unroll
        for (int c = 0; c < NC; c++) atomicAdd(&sb[c * OD + l], fp[c * PIX]);
    }
    __syncthreads();
    for (int i = t; i < NC * OD; i += 256) {
        int c = i / OD, l = i - c * OD;
        atomicAdd(&g_sums[(n * OD + l) * NC + c], sb[i]);
    }
    if (t < OD) atomicAdd(&g_cnt[n * OD + t], sc[t]);
}

// 1 block 256 threads: compute means, then cls_fea (max over occupied segments)
__global__ void k_finish(float* __restrict__ cls_fea) {
    int t = threadIdx.x;   // t = seg index n*32+s
    float cnt = g_cnt[t];
    float inv = 1.f / fmaxf(cnt, 1.f);
    for (int c = 0; c < NC; c++) g_means[t * NC + c] = g_sums[t * NC + c] * inv;
    __syncthreads();
    if (t < N_IMG * NC) {
        int n = t / NC, c = t - n * NC;
        float m = -INFINITY;
        for (int s = 0; s < OD; s++)
            if (g_cnt[n * OD + s] > 0.f) m = fmaxf(m, g_means[(n * OD + s) * NC + c]);
        cls_fea[t] = m;
    }
}

// scatter means back: features[n][c][p] = means[n][lab[p]][c]
__global__ void k_scatter(float* __restrict__ out_feat) {
    int idx = blockIdx.x * 256 + threadIdx.x;   // < 8*20*65536
    int p = idx & 65535;
    int nc = idx >> 16;
    int c = nc % NC, n = nc / NC;
    int l = g_lab[n * PIX + p];
    out_feat[idx] = g_means[(n * OD + l) * NC + c];
}

// ---------------- launch ----------------
extern "C" void kernel_launch(void* const* d_in, const int* in_sizes, int n_in,
                              void* d_out, int out_size) {
    const float* x   = (const float*)d_in[0];
    const float* x4  = (const float*)d_in[1];
    const float* Wc  = (const float*)d_in[2];
    const float* W1  = (const float*)d_in[3];
    const float* b1c = (const float*)d_in[4];
    const float* g1  = (const float*)d_in[5];
    const float* be1 = (const float*)d_in[6];
    const float* m1  = (const float*)d_in[7];
    const float* v1  = (const float*)d_in[8];
    const float* W2  = (const float*)d_in[9];
    const float* b2c = (const float*)d_in[10];
    const float* g2  = (const float*)d_in[11];
    const float* be2 = (const float*)d_in[12];
    const float* m2  = (const float*)d_in[13];
    const float* v2  = (const float*)d_in[14];
    const float* W3  = (const float*)d_in[15];
    const float* b3c = (const float*)d_in[16];
    const float* g3  = (const float*)d_in[17];
    const float* be3 = (const float*)d_in[18];
    const float* m3  = (const float*)d_in[19];
    const float* v3  = (const float*)d_in[20];

    float* out      = (float*)d_out;
    float* out_cls  = out;                       // [8,20]
    float* out_cfea = out + 160;                 // [8,20]
    float* out_feat = out + 320;                 // [8,20,256,256]
    float* out_mask = out + 320 + N_IMG*NC*PIX;  // [8,32,256,256]

    k_bnprep<<<1, 256>>>(g1, be1, m1, v1, g2, be2, m2, v2, g3, be3, m3, v3);
    k_classifier<<<N_IMG * NC, 256>>>(x4, Wc, out_cls);
    k_up<<<(N_IMG * NC * PIX) / 256, 256>>>();
    k_down<<<(N_IMG * 3 * PIX) / 256, 256>>>(x);
    k_conv1<<<dim3(PIX / 256, 25, N_IMG), 256>>>(W1, b1c);
    k_conv2<<<dim3(256, CH / OCT, N_IMG), 128>>>(W2, b2c);
    k_conv3<<<dim3(PIX / 256, N_IMG), 256>>>(W3, b3c, out_mask);
    k_zero<<<21, 256>>>();
    k_segsum<<<dim3(16, N_IMG), 256>>>();
    k_finish<<<1, 256>>>(out_cfea);
    k_scatter<<<(N_IMG * NC * PIX) / 256, 256>>>(out_feat);
}

// round 3
// speedup vs baseline: 1.8936x; 1.8936x over previous
#include <cuda_runtime.h>
#include <cuda_bf16.h>
#include <math.h>

#define N_IMG 8
#define CH    100
#define OD    32
#define NC    20
#define HH    256
#define WW    256
#define PIX   (HH*WW)      // 65536

// ---------------- scratch (static device globals; no allocations) ----------------
__device__ float g_xs  [N_IMG*3*PIX];
__device__ float g_fs  [N_IMG*NC*256];
__device__ float g_fup [N_IMG*NC*PIX];
__device__ float g_y1  [N_IMG*CH*PIX];
__device__ float g_y2  [N_IMG*CH*PIX];
__device__ int   g_lab [N_IMG*PIX];
__device__ float g_sums[N_IMG*OD*NC];
__device__ float g_cnt [N_IMG*OD];
__device__ float g_means[N_IMG*OD*NC];
// bn params: [0,100)=s1 [100,200)=t1 [200,300)=s2 [300,400)=t2 [400,432)=s3 [432,464)=t3
__device__ float g_bnp[464];
// pre-swizzled bf16 weight images for conv2 mma path:
// [chunk 7][tapgroup 3] blocks of 10752B; within block: rows q = dxi*112 + n (32B, swizzled)
__device__ unsigned char g_Wb2h[7*3*10752];
__device__ unsigned char g_Wb2l[7*3*10752];

// ======== warp-mma helpers (family-safe PTX, sm_80+) ========
__device__ __forceinline__ unsigned smem_u32(const void* p) {
    unsigned a;
    asm("{ .reg .u64 t; cvta.to.shared.u64 t, %1; cvt.u32.u64 %0, t; }" : "=r"(a) : "l"(p));
    return a;
}
__device__ __forceinline__ void mma16816(float* d, const unsigned* a, unsigned b0, unsigned b1) {
    asm volatile("mma.sync.aligned.m16n8k16.row.col.f32.bf16.bf16.f32 "
        "{%0,%1,%2,%3}, {%4,%5,%6,%7}, {%8,%9}, {%0,%1,%2,%3};"
        : "+f"(d[0]), "+f"(d[1]), "+f"(d[2]), "+f"(d[3])
        : "r"(a[0]), "r"(a[1]), "r"(a[2]), "r"(a[3]), "r"(b0), "r"(b1));
}
__device__ __forceinline__ void ldsm4(unsigned* r, unsigned addr) {
    asm volatile("ldmatrix.sync.aligned.m8n8.x4.shared.b16 {%0,%1,%2,%3}, [%4];"
        : "=r"(r[0]), "=r"(r[1]), "=r"(r[2]), "=r"(r[3]) : "r"(addr));
}
__device__ __forceinline__ void ldsm2(unsigned* r, unsigned addr) {
    asm volatile("ldmatrix.sync.aligned.m8n8.x2.shared.b16 {%0,%1}, [%2];"
        : "=r"(r[0]), "=r"(r[1]) : "r"(addr));
}

// ---------------- bn prep ----------------
__global__ void k_bnprep(const float* g1, const float* be1, const float* m1, const float* v1,
                         const float* g2, const float* be2, const float* m2, const float* v2,
                         const float* g3, const float* be3, const float* m3, const float* v3) {
    int t = threadIdx.x;
    if (t < 100) {
        float s = g1[t] / sqrtf(v1[t] + 1e-5f);
        g_bnp[t] = s; g_bnp[100 + t] = be1[t] - m1[t] * s;
    } else if (t < 200) {
        int i = t - 100;
        float s = g2[i] / sqrtf(v2[i] + 1e-5f);
        g_bnp[200 + i] = s; g_bnp[300 + i] = be2[i] - m2[i] * s;
    } else if (t < 232) {
        int i = t - 200;
        float s = g3[i] / sqrtf(v3[i] + 1e-5f);
        g_bnp[400 + i] = s; g_bnp[432 + i] = be3[i] - m3[i] * s;
    }
}

// ---------------- conv2 weight prep: hi/lo bf16 split, pre-swizzled ----------------
__global__ void k_wprep(const float* __restrict__ W2) {
    int idx = blockIdx.x * 256 + threadIdx.x;   // total 7*9*112*16 = 112896
    if (idx >= 112896) return;
    int c = idx / 16128;                 // chunk
    int rem = idx - c * 16128;
    int tap = rem / 1792;                // 0..8 = (dy+1)*3 + (dx+1)
    int rem2 = rem - tap * 1792;
    int nn = rem2 >> 4;                  // oc 0..111
    int k  = rem2 & 15;                  // ic within chunk
    int ic = c * 16 + k;
    float v = 0.f;
    if (nn < 100 && ic < 100) v = W2[nn * 900 + ic * 9 + tap];
    __nv_bfloat16 h = __float2bfloat16(v);
    __nv_bfloat16 l = __float2bfloat16(v - __bfloat162float(h));
    int tg = tap / 3, tl = tap - tg * 3;
    int q = tl * 112 + nn;
    unsigned off = (unsigned)((c * 3 + tg) * 10752 + q * 32
                 + ((((k >> 3) ^ (q >> 2)) & 1) << 4) + (k & 7) * 2);
    *(__nv_bfloat16*)(g_Wb2h + off) = h;
    *(__nv_bfloat16*)(g_Wb2l + off) = l;
}

// ---------------- classifier 1x1 conv + spatial max ----------------
__global__ void k_classifier(const float* __restrict__ x4, const float* __restrict__ Wc,
                             float* __restrict__ cls_out) {
    int b = blockIdx.x;
    int n = b / NC, oc = b % NC;
    __shared__ float wsh[512];
    __shared__ float red[256];
    int t = threadIdx.x;
    wsh[t]       = Wc[oc * 512 + t];
    wsh[t + 256] = Wc[oc * 512 + t + 256];
    __syncthreads();
    const float* xp = x4 + (long)n * 512 * 256;
    float acc = 0.f;
    #pragma unroll 8
    for (int c = 0; c < 512; c++) acc = fmaf(xp[c * 256 + t], wsh[c], acc);
    g_fs[(n * NC + oc) * 256 + t] = acc;
    red[t] = acc; __syncthreads();
    for (int s = 128; s > 0; s >>= 1) {
        if (t < s) red[t] = fmaxf(red[t], red[t + s]);
        __syncthreads();
    }
    if (t == 0) cls_out[n * NC + oc] = red[0];
}

// ---------------- bilinear upsample 16 -> 256 ----------------
__global__ void k_up() {
    int idx = blockIdx.x * 256 + threadIdx.x;
    int x = idx & 255;
    int y = (idx >> 8) & 255;
    int nc = idx >> 16;
    float sy = (y + 0.5f) * 0.0625f - 0.5f;
    float sx = (x + 0.5f) * 0.0625f - 0.5f;
    float fy0 = floorf(sy), fx0 = floorf(sx);
    float fy = sy - fy0, fx = sx - fx0;
    int y0 = max((int)fy0, 0), y1 = min((int)fy0 + 1, 15);
    int x0 = max((int)fx0, 0), x1 = min((int)fx0 + 1, 15);
    const float* fs = g_fs + nc * 256;
    float v00 = fs[y0 * 16 + x0], v01 = fs[y0 * 16 + x1];
    float v10 = fs[y1 * 16 + x0], v11 = fs[y1 * 16 + x1];
    float v = (v00 * (1.f - fx) + v01 * fx) * (1.f - fy) + (v10 * (1.f - fx) + v11 * fx) * fy;
    g_fup[idx] = v;
}

// ---------------- antialiased bilinear downsample 512 -> 256 ----------------
__device__ __forceinline__ float d_taps(int d, int* ix, float* wv) {
    float s = 0.f;
    #pragma unroll
    for (int i = 0; i < 4; i++) {
        int p = 2 * d - 1 + i;
        float w = (i == 0 || i == 3) ? 1.f : 3.f;
        if (p < 0 || p >= 512) { w = 0.f; p = p < 0 ? 0 : 511; }
        ix[i] = p; wv[i] = w; s += w;
    }
    return s;
}

__global__ void k_down(const float* __restrict__ x) {
    int idx = blockIdx.x * 256 + threadIdx.x;
    int xo = idx & 255;
    int yo = (idx >> 8) & 255;
    int nc = idx >> 16;
    int iy[4], ixs[4];
    float wy[4], wx[4];
    float ny = d_taps(yo, iy, wy);
    float nx = d_taps(xo, ixs, wx);
    const float* xp = x + (long)nc * 512 * 512;
    float acc = 0.f;
    #pragma unroll
    for (int i = 0; i < 4; i++) {
        const float* row = xp + iy[i] * 512;
        float r = wx[0]*row[ixs[0]] + wx[1]*row[ixs[1]] + wx[2]*row[ixs[2]] + wx[3]*row[ixs[3]];
        acc += wy[i] * r;
    }
    g_xs[idx] = acc / (ny * nx);
}

// ---------------- conv1: 3x3, 3->100 ----------------
__global__ void k_conv1(const float* __restrict__ W1, const float* __restrict__ b1) {
    __shared__ float ws[4 * 27];
    __shared__ float bs[4], ss[4], ts[4];
    int t = threadIdx.x;
    int n = blockIdx.z, ocg = blockIdx.y;
    if (t < 108) ws[t] = W1[ocg * 108 + t];
    if (t < 4) {
        int oc = ocg * 4 + t;
        bs[t] = b1[oc]; ss[t] = g_bnp[oc]; ts[t] = g_bnp[100 + oc];
    }
    __syncthreads();
    int p = blockIdx.x * 256 + t;
    int y = p >> 8, x = p & 255;
    const float* xp = g_xs + n * 3 * PIX;
    float in[27];
    int k = 0;
    #pragma unroll
    for (int c = 0; c < 3; c++)
        #pragma unroll
        for (int dy = -1; dy <= 1; dy++) {
            int yy = y + dy;
            #pragma unroll
            for (int dx = -1; dx <= 1; dx++) {
                int xx = x + dx;
                in[k++] = ((unsigned)yy < 256u && (unsigned)xx < 256u) ? xp[c * PIX + yy * 256 + xx] : 0.f;
            }
        }
    #pragma unroll
    for (int o = 0; o < 4; o++) {
        float a = bs[o];
        #pragma unroll
        for (int j = 0; j < 27; j++) a = fmaf(in[j], ws[o * 27 + j], a);
        a = fmaxf(a, 0.f);
        a = fmaf(a, ss[o], ts[o]);
        g_y1[((n * CH + ocg * 4 + o) * PIX) + p] = a;
    }
}

// ---------------- conv2: warp-mma implicit GEMM (9 shifted GEMMs over ic) ----------------
// CTA tile: M=128 pixels (one row) x N=112 oc (100 real), K = 7 chunks x 16 ic.
// 8 warps as 4(M) x 2(N): warp = 2 m16-subs x 7 n8-tiles. 3-pass bf16 hi/lo split.
__global__ __launch_bounds__(256, 2) void k_conv2m(const float* __restrict__ b2) {
    __shared__ __align__(16) unsigned char sAh[12480], sAl[12480];   // [3r][130c] rows of 32B
    __shared__ __align__(16) unsigned char sBh[10752], sBl[10752];   // [3 dxi][112 n] rows of 32B
    __shared__ float sEp[3][112];

    int t = threadIdx.x, lane = t & 31, wid = t >> 5;
    int wm = wid & 3, wn = wid >> 2;
    int x0 = blockIdx.x * 128, y = blockIdx.y, n = blockIdx.z;

    if (t < 112) {
        float bb = 0.f, sc = 0.f, sh = 0.f;
        if (t < 100) { bb = b2[t]; sc = g_bnp[200 + t]; sh = g_bnp[300 + t]; }
        sEp[0][t] = bb; sEp[1][t] = sc; sEp[2][t] = sh;
    }

    unsigned baseAh = smem_u32(sAh), baseAl = smem_u32(sAl);
    unsigned baseBh = smem_u32(sBh), baseBl = smem_u32(sBl);

    // ldmatrix lane constants
    int arow = (lane & 7) + ((lane >> 3) & 1) * 8;   // A: row within m16
    int akb3 = (lane >> 4) & 1;                       // A: k-halfblock select
    int brow = lane & 7;                              // B: n row within tile
    int btsel = (lane >> 4) & 1;                      // B: tile pair select
    int bkb3 = (lane >> 3) & 1;                       // B: k-halfblock select

    float acc[2][7][4];
    #pragma unroll
    for (int s = 0; s < 2; s++)
        #pragma unroll
        for (int j = 0; j < 7; j++)
            #pragma unroll
            for (int e = 0; e < 4; e++) acc[s][j][e] = 0.f;

    const float* src = g_y1 + (long)n * CH * PIX;

    for (int ch = 0; ch < 7; ch++) {
        __syncthreads();   // previous chunk fully consumed
        // ---- stage A: 16 ic x 3 rows x 130 cols, bf16 hi/lo, swizzled ----
        int ic0 = ch * 16;
        for (int i = t; i < 6240; i += 256) {
            int k = i / 390;
            int rem = i - k * 390;
            int r = rem / 130;
            int cc = rem - r * 130;
            float v = 0.f;
            int ic = ic0 + k, yy = y - 1 + r, xx = x0 - 1 + cc;
            if (ic < 100 && (unsigned)yy < 256u && (unsigned)xx < 256u)
                v = src[ic * PIX + yy * 256 + xx];
            __nv_bfloat16 h = __float2bfloat16(v);
            __nv_bfloat16 l = __float2bfloat16(v - __bfloat162float(h));
            int p = r * 130 + cc;
            unsigned off = (unsigned)(p * 32 + ((((k >> 3) ^ (p >> 2)) & 1) << 4) + (k & 7) * 2);
            *(__nv_bfloat16*)(sAh + off) = h;
            *(__nv_bfloat16*)(sAl + off) = l;
        }
        for (int tg = 0; tg < 3; tg++) {       // tg = dy index
            __syncthreads();
            {   // ---- load B group (3 dx-taps), flat copy of pre-swizzled image ----
                const uint4* gh = (const uint4*)(g_Wb2h + (ch * 3 + tg) * 10752);
                const uint4* gl = (const uint4*)(g_Wb2l + (ch * 3 + tg) * 10752);
                uint4* dh = (uint4*)sBh; uint4* dl = (uint4*)sBl;
                for (int i = t; i < 672; i += 256) { dh[i] = gh[i]; dl[i] = gl[i]; }
            }
            __syncthreads();
            #pragma unroll
            for (int dxi = 0; dxi < 3; dxi++) {
                unsigned ah[2][4], al[2][4];
                #pragma unroll
                for (int s = 0; s < 2; s++) {
                    int pa = tg * 130 + wm * 32 + dxi + s * 16 + arow;
                    unsigned aoff = (unsigned)(pa * 32 + ((akb3 ^ ((pa >> 2) & 1)) << 4));
                    ldsm4(ah[s], baseAh + aoff);
                    ldsm4(al[s], baseAl + aoff);
                }
                #pragma unroll
                for (int jp = 0; jp < 3; jp++) {
                    int j0 = wn * 7 + jp * 2;
                    int q = dxi * 112 + (j0 + btsel) * 8 + brow;
                    unsigned boff = (unsigned)(q * 32 + ((bkb3 ^ ((q >> 2) & 1)) << 4));
                    unsigned bh[4], bl[4];
                    ldsm4(bh, baseBh + boff);
                    ldsm4(bl, baseBl + boff);
                    #pragma unroll
                    for (int tl = 0; tl < 2; tl++) {
                        #pragma unroll
                        for (int s = 0; s < 2; s++) {
                            float* d = acc[s][jp * 2 + tl];
                            mma16816(d, ah[s], bh[2 * tl], bh[2 * tl + 1]);
                            mma16816(d, al[s], bh[2 * tl], bh[2 * tl + 1]);
                            mma16816(d, ah[s], bl[2 * tl], bl[2 * tl + 1]);
                        }
                    }
                }
                {   // tail tile j = 6
                    int j6 = wn * 7 + 6;
                    int q = dxi * 112 + j6 * 8 + brow;
                    unsigned boff = (unsigned)(q * 32 + ((bkb3 ^ ((q >> 2) & 1)) << 4));
                    unsigned bh[2], bl[2];
                    ldsm2(bh, baseBh + boff);
                    ldsm2(bl, baseBl + boff);
                    #pragma unroll
                    for (int s = 0; s < 2; s++) {
                        float* d = acc[s][6];
                        mma16816(d, ah[s], bh[0], bh[1]);
                        mma16816(d, al[s], bh[0], bh[1]);
                        mma16816(d, ah[s], bl[0], bl[1]);
                    }
                }
            }
        }
    }

    // ---- epilogue: bias + relu + bn, write NCHW ----
    int rbase = wm * 32 + (lane >> 2);
    int ocl = (lane & 3) * 2;
    #pragma unroll
    for (int s = 0; s < 2; s++) {
        int pix0 = y * 256 + x0 + rbase + s * 16;
        #pragma unroll
        for (int j = 0; j < 7; j++) {
            int oc0 = (wn * 7 + j) * 8 + ocl;
            #pragma unroll
            for (int hh = 0; hh < 2; hh++) {
                int pp = pix0 + hh * 8;
                #pragma unroll
                for (int e = 0; e < 2; e++) {
                    int oc = oc0 + e;
                    if (oc < 100) {
                        float v = acc[s][j][hh * 2 + e];
                        v = fmaf(fmaxf(v + sEp[0][oc], 0.f), sEp[1][oc], sEp[2][oc]);
                        g_y2[(long)(n * CH + oc) * PIX + pp] = v;
                    }
                }
            }
        }
    }
}

// ---------------- conv3: 1x1, 100->32 + bn + argmax ----------------
__global__ void k_conv3(const float* __restrict__ W3, const float* __restrict__ b3,
                        float* __restrict__ out_mask) {
    __shared__ float w3s[100 * 32];
    __shared__ float p3[96];
    int t = threadIdx.x, n = blockIdx.y;
    for (int i = t; i < 3200; i += 256) {
        int oc = i & 31, c = i >> 5;
        w3s[i] = W3[oc * 100 + c];
    }
    if (t < 32) { p3[t] = b3[t]; p3[32 + t] = g_bnp[400 + t]; p3[64 + t] = g_bnp[432 + t]; }
    __syncthreads();
    int p = blockIdx.x * 256 + t;
    const float* yp = g_y2 + (long)n * CH * PIX + p;
    float acc[32];
    #pragma unroll
    for (int o = 0; o < 32; o++) acc[o] = 0.f;
    for (int c = 0; c < 100; c++) {
        float v = yp[c * PIX];
        #pragma unroll
        for (int o = 0; o < 32; o++) acc[o] = fmaf(v, w3s[c * 32 + o], acc[o]);
    }
    float best = -INFINITY;
    int bi = 0;
    #pragma unroll
    for (int o = 0; o < 32; o++) {
        float m = fmaf(acc[o] + p3[o], p3[32 + o], p3[64 + o]);
        out_mask[(long)(n * OD + o) * PIX + p] = m;
        if (m > best) { best = m; bi = o; }
    }
    g_lab[n * PIX + p] = bi;
}

// ---------------- segment stats ----------------
__global__ void k_zero() {
    int i = blockIdx.x * 256 + threadIdx.x;
    if (i < N_IMG * OD * NC) g_sums[i] = 0.f;
    if (i < N_IMG * OD) g_cnt[i] = 0.f;
}

__global__ void k_segsum() {
    __shared__ float sb[NC * OD];
    __shared__ float sc[OD];
    int t = threadIdx.x, n = blockIdx.y;
    for (int i = t; i < NC * OD; i += 256) sb[i] = 0.f;
    if (t < OD) sc[t] = 0.f;
    __syncthreads();
    int pbase = blockIdx.x * 4096;
    for (int it = 0; it < 16; it++) {
        int p = pbase + it * 256 + t;
        int l = g_lab[n * PIX + p];
        atomicAdd(&sc[l], 1.f);
        const float* fp = g_fup + (long)n * NC * PIX + p;
        #pragma unroll
        for (int c = 0; c < NC; c++) atomicAdd(&sb[c * OD + l], fp[c * PIX]);
    }
    __syncthreads();
    for (int i = t; i < NC * OD; i += 256) {
        int c = i / OD, l = i - c * OD;
        atomicAdd(&g_sums[(n * OD + l) * NC + c], sb[i]);
    }
    if (t < OD) atomicAdd(&g_cnt[n * OD + t], sc[t]);
}

__global__ void k_finish(float* __restrict__ cls_fea) {
    int t = threadIdx.x;
    float cnt = g_cnt[t];
    float inv = 1.f / fmaxf(cnt, 1.f);
    for (int c = 0; c < NC; c++) g_means[t * NC + c] = g_sums[t * NC + c] * inv;
    __syncthreads();
    if (t < N_IMG * NC) {
        int n = t / NC, c = t - n * NC;
        float m = -INFINITY;
        for (int s = 0; s < OD; s++)
            if (g_cnt[n * OD + s] > 0.f) m = fmaxf(m, g_means[(n * OD + s) * NC + c]);
        cls_fea[t] = m;
    }
}

__global__ void k_scatter(float* __restrict__ out_feat) {
    int idx = blockIdx.x * 256 + threadIdx.x;
    int p = idx & 65535;
    int nc = idx >> 16;
    int c = nc % NC, n = nc / NC;
    int l = g_lab[n * PIX + p];
    out_feat[idx] = g_means[(n * OD + l) * NC + c];
}

// ---------------- launch ----------------
extern "C" void kernel_launch(void* const* d_in, const int* in_sizes, int n_in,
                              void* d_out, int out_size) {
    const float* x   = (const float*)d_in[0];
    const float* x4  = (const float*)d_in[1];
    const float* Wc  = (const float*)d_in[2];
    const float* W1  = (const float*)d_in[3];
    const float* b1c = (const float*)d_in[4];
    const float* g1  = (const float*)d_in[5];
    const float* be1 = (const float*)d_in[6];
    const float* m1  = (const float*)d_in[7];
    const float* v1  = (const float*)d_in[8];
    const float* W2  = (const float*)d_in[9];
    const float* b2c = (const float*)d_in[10];
    const float* g2  = (const float*)d_in[11];
    const float* be2 = (const float*)d_in[12];
    const float* m2  = (const float*)d_in[13];
    const float* v2  = (const float*)d_in[14];
    const float* W3  = (const float*)d_in[15];
    const float* b3c = (const float*)d_in[16];
    const float* g3  = (const float*)d_in[17];
    const float* be3 = (const float*)d_in[18];
    const float* m3  = (const float*)d_in[19];
    const float* v3  = (const float*)d_in[20];

    float* out      = (float*)d_out;
    float* out_cls  = out;
    float* out_cfea = out + 160;
    float* out_feat = out + 320;
    float* out_mask = out + 320 + N_IMG*NC*PIX;

    k_bnprep<<<1, 256>>>(g1, be1, m1, v1, g2, be2, m2, v2, g3, be3, m3, v3);
    k_wprep<<<441, 256>>>(W2);
    k_classifier<<<N_IMG * NC, 256>>>(x4, Wc, out_cls);
    k_up<<<(N_IMG * NC * PIX) / 256, 256>>>();
    k_down<<<(N_IMG * 3 * PIX) / 256, 256>>>(x);
    k_conv1<<<dim3(PIX / 256, 25, N_IMG), 256>>>(W1, b1c);
    k_conv2m<<<dim3(2, 256, N_IMG), 256>>>(b2c);
    k_conv3<<<dim3(PIX / 256, N_IMG), 256>>>(W3, b3c, out_mask);
    k_zero<<<21, 256>>>();
    k_segsum<<<dim3(16, N_IMG), 256>>>();
    k_finish<<<1, 256>>>(out_cfea);
    k_scatter<<<(N_IMG * NC * PIX) / 256, 256>>>(out_feat);
}

// round 4
// speedup vs baseline: 2.2947x; 1.2118x over previous
#include <cuda_runtime.h>
#include <cuda_bf16.h>
#include <math.h>

#define N_IMG 8
#define CH    100
#define OD    32
#define NC    20
#define HH    256
#define WW    256
#define PIX   (HH*WW)      // 65536

// ---------------- scratch (static device globals; no allocations) ----------------
__device__ float g_xs  [N_IMG*3*PIX];
__device__ float g_fs  [N_IMG*NC*256];
__device__ float g_fup [N_IMG*NC*PIX];
__device__ float g_y2  [N_IMG*CH*PIX];
__device__ int   g_lab [N_IMG*PIX];
__device__ float g_sums[N_IMG*OD*NC];
__device__ float g_cnt [N_IMG*OD];
__device__ float g_means[N_IMG*OD*NC];
// bn params: [0,100)=s1 [100,200)=t1 [200,300)=s2 [300,400)=t2 [400,432)=s3 [432,464)=t3
__device__ float g_bnp[464];
// y1 in NHWC bf16 hi/lo, channel pitch 112 (channels >=100 zeroed). uint4-addressable.
__device__ uint4 g_y1h4[(size_t)N_IMG*PIX*14];
__device__ uint4 g_y1l4[(size_t)N_IMG*PIX*14];
// conv2 B fragments: [chunk 7][tap 9][tile 14][lane 32] uint4 = {bh0,bh1,bl0,bl1}
__device__ uint4 g_WB[7*9*14*32];

// ======== warp-mma helpers (family-safe PTX, sm_80+) ========
__device__ __forceinline__ unsigned smem_u32(const void* p) {
    unsigned a;
    asm("{ .reg .u64 t; cvta.to.shared.u64 t, %1; cvt.u32.u64 %0, t; }" : "=r"(a) : "l"(p));
    return a;
}
__device__ __forceinline__ void mma16816(float* d, const unsigned* a, unsigned b0, unsigned b1) {
    asm volatile("mma.sync.aligned.m16n8k16.row.col.f32.bf16.bf16.f32 "
        "{%0,%1,%2,%3}, {%4,%5,%6,%7}, {%8,%9}, {%0,%1,%2,%3};"
        : "+f"(d[0]), "+f"(d[1]), "+f"(d[2]), "+f"(d[3])
        : "r"(a[0]), "r"(a[1]), "r"(a[2]), "r"(a[3]), "r"(b0), "r"(b1));
}
__device__ __forceinline__ void ldsm4(unsigned* r, unsigned addr) {
    asm volatile("ldmatrix.sync.aligned.m8n8.x4.shared.b16 {%0,%1,%2,%3}, [%4];"
        : "=r"(r[0]), "=r"(r[1]), "=r"(r[2]), "=r"(r[3]) : "r"(addr));
}
__device__ __forceinline__ unsigned pk2(float a, float b) {
    unsigned lo = (unsigned)__bfloat16_as_ushort(__float2bfloat16(a));
    unsigned hi = (unsigned)__bfloat16_as_ushort(__float2bfloat16(b));
    return lo | (hi << 16);
}

// ---------------- bn prep ----------------
__global__ void k_bnprep(const float* g1, const float* be1, const float* m1, const float* v1,
                         const float* g2, const float* be2, const float* m2, const float* v2,
                         const float* g3, const float* be3, const float* m3, const float* v3) {
    int t = threadIdx.x;
    if (t < 100) {
        float s = g1[t] / sqrtf(v1[t] + 1e-5f);
        g_bnp[t] = s; g_bnp[100 + t] = be1[t] - m1[t] * s;
    } else if (t < 200) {
        int i = t - 100;
        float s = g2[i] / sqrtf(v2[i] + 1e-5f);
        g_bnp[200 + i] = s; g_bnp[300 + i] = be2[i] - m2[i] * s;
    } else if (t < 232) {
        int i = t - 200;
        float s = g3[i] / sqrtf(v3[i] + 1e-5f);
        g_bnp[400 + i] = s; g_bnp[432 + i] = be3[i] - m3[i] * s;
    }
}

// ---------------- conv2 weight prep: per-lane mma B fragments ----------------
__global__ void k_wprep(const float* __restrict__ W2) {
    int idx = blockIdx.x * 256 + threadIdx.x;   // 7*9*14*32 = 28224
    if (idx >= 28224) return;
    int l = idx & 31;
    int j = (idx >> 5) % 14;
    int tap = (idx / (32 * 14)) % 9;
    int c = idx / (32 * 14 * 9);
    int nn = j * 8 + (l >> 2);
    int k0 = (l & 3) * 2;
    float vh[4], vl[4];
    #pragma unroll
    for (int e = 0; e < 4; e++) {
        int k = k0 + (e & 1) + (e >> 1) * 8;   // k0, k0+1, k0+8, k0+9
        int ic = c * 16 + k;
        float v = 0.f;
        if (nn < 100 && ic < 100) v = W2[nn * 900 + ic * 9 + tap];
        float h = __bfloat162float(__float2bfloat16(v));
        vh[e] = h; vl[e] = v - h;
    }
    uint4 w;
    w.x = pk2(vh[0], vh[1]);
    w.y = pk2(vh[2], vh[3]);
    w.z = pk2(vl[0], vl[1]);
    w.w = pk2(vl[2], vl[3]);
    g_WB[idx] = w;
}

// ---------------- classifier 1x1 conv + spatial max ----------------
__global__ void k_classifier(const float* __restrict__ x4, const float* __restrict__ Wc,
                             float* __restrict__ cls_out) {
    int b = blockIdx.x;
    int n = b / NC, oc = b % NC;
    __shared__ float wsh[512];
    __shared__ float red[256];
    int t = threadIdx.x;
    wsh[t]       = Wc[oc * 512 + t];
    wsh[t + 256] = Wc[oc * 512 + t + 256];
    __syncthreads();
    const float* xp = x4 + (long)n * 512 * 256;
    float acc = 0.f;
    #pragma unroll 8
    for (int c = 0; c < 512; c++) acc = fmaf(xp[c * 256 + t], wsh[c], acc);
    g_fs[(n * NC + oc) * 256 + t] = acc;
    red[t] = acc; __syncthreads();
    for (int s = 128; s > 0; s >>= 1) {
        if (t < s) red[t] = fmaxf(red[t], red[t + s]);
        __syncthreads();
    }
    if (t == 0) cls_out[n * NC + oc] = red[0];
}

// ---------------- bilinear upsample 16 -> 256 ----------------
__global__ void k_up() {
    int idx = blockIdx.x * 256 + threadIdx.x;
    int x = idx & 255;
    int y = (idx >> 8) & 255;
    int nc = idx >> 16;
    float sy = (y + 0.5f) * 0.0625f - 0.5f;
    float sx = (x + 0.5f) * 0.0625f - 0.5f;
    float fy0 = floorf(sy), fx0 = floorf(sx);
    float fy = sy - fy0, fx = sx - fx0;
    int y0 = max((int)fy0, 0), y1 = min((int)fy0 + 1, 15);
    int x0 = max((int)fx0, 0), x1 = min((int)fx0 + 1, 15);
    const float* fs = g_fs + nc * 256;
    float v00 = fs[y0 * 16 + x0], v01 = fs[y0 * 16 + x1];
    float v10 = fs[y1 * 16 + x0], v11 = fs[y1 * 16 + x1];
    float v = (v00 * (1.f - fx) + v01 * fx) * (1.f - fy) + (v10 * (1.f - fx) + v11 * fx) * fy;
    g_fup[idx] = v;
}

// ---------------- antialiased bilinear downsample 512 -> 256 ----------------
__device__ __forceinline__ float d_taps(int d, int* ix, float* wv) {
    float s = 0.f;
    #pragma unroll
    for (int i = 0; i < 4; i++) {
        int p = 2 * d - 1 + i;
        float w = (i == 0 || i == 3) ? 1.f : 3.f;
        if (p < 0 || p >= 512) { w = 0.f; p = p < 0 ? 0 : 511; }
        ix[i] = p; wv[i] = w; s += w;
    }
    return s;
}

__global__ void k_down(const float* __restrict__ x) {
    int idx = blockIdx.x * 256 + threadIdx.x;
    int xo = idx & 255;
    int yo = (idx >> 8) & 255;
    int nc = idx >> 16;
    int iy[4], ixs[4];
    float wy[4], wx[4];
    float ny = d_taps(yo, iy, wy);
    float nx = d_taps(xo, ixs, wx);
    const float* xp = x + (long)nc * 512 * 512;
    float acc = 0.f;
    #pragma unroll
    for (int i = 0; i < 4; i++) {
        const float* row = xp + iy[i] * 512;
        float r = wx[0]*row[ixs[0]] + wx[1]*row[ixs[1]] + wx[2]*row[ixs[2]] + wx[3]*row[ixs[3]];
        acc += wy[i] * r;
    }
    g_xs[idx] = acc / (ny * nx);
}

// ---------------- conv1: 3x3, 3->100, write NHWC bf16 hi/lo (pitch 112) ----------------
// grid: (512 pixblocks, 8 n), 128 threads; each thread = 1 pixel, all 112 channels
__global__ void k_conv1(const float* __restrict__ W1, const float* __restrict__ b1) {
    __shared__ float ws[2700];
    __shared__ float bs[100], ss[100], ts[100];
    int t = threadIdx.x, n = blockIdx.y;
    for (int i = t; i < 2700; i += 128) ws[i] = W1[i];
    if (t < 100) { bs[t] = b1[t]; ss[t] = g_bnp[t]; ts[t] = g_bnp[100 + t]; }
    __syncthreads();
    int p = blockIdx.x * 128 + t;
    int y = p >> 8, x = p & 255;
    const float* xp = g_xs + n * 3 * PIX;
    float in[27];
    int k = 0;
    #pragma unroll
    for (int c = 0; c < 3; c++)
        #pragma unroll
        for (int dy = -1; dy <= 1; dy++) {
            int yy = y + dy;
            #pragma unroll
            for (int dx = -1; dx <= 1; dx++) {
                int xx = x + dx;
                in[k++] = ((unsigned)yy < 256u && (unsigned)xx < 256u) ? xp[c * PIX + yy * 256 + xx] : 0.f;
            }
        }
    long obase = ((long)n * PIX + p) * 14;
    for (int oc0 = 0; oc0 < 112; oc0 += 8) {
        unsigned hw[4], lw[4];
        #pragma unroll
        for (int e2 = 0; e2 < 4; e2++) {
            float v[2];
            #pragma unroll
            for (int u = 0; u < 2; u++) {
                int oc = oc0 + e2 * 2 + u;
                float a = 0.f;
                if (oc < 100) {
                    a = bs[oc];
                    const float* w = ws + oc * 27;
                    #pragma unroll
                    for (int j = 0; j < 27; j++) a = fmaf(in[j], w[j], a);
                    a = fmaxf(a, 0.f);
                    a = fmaf(a, ss[oc], ts[oc]);
                }
                v[u] = a;
            }
            float h0 = __bfloat162float(__float2bfloat16(v[0]));
            float h1 = __bfloat162float(__float2bfloat16(v[1]));
            hw[e2] = pk2(v[0], v[1]);
            lw[e2] = pk2(v[0] - h0, v[1] - h1);
        }
        g_y1h4[obase + (oc0 >> 3)] = make_uint4(hw[0], hw[1], hw[2], hw[3]);
        g_y1l4[obase + (oc0 >> 3)] = make_uint4(lw[0], lw[1], lw[2], lw[3]);
    }
}

// ---------------- conv2: warp-mma implicit GEMM, cp.async A pipeline, LDG B frags ----
// CTA tile: M=128 pixels x N=112 oc; K = 7 chunks x 16 ic; 9 taps as shifted GEMMs.
// dynamic smem: 2 stages x (Ah 12480 + Al 12480) = 49920 bytes
#define C2_AH    12480
#define C2_STG   24960
#define C2_SMEM  49920

__global__ __launch_bounds__(256, 2) void k_conv2m(const float* __restrict__ b2) {
    extern __shared__ __align__(16) unsigned char dsm[];
    __shared__ float sEp[3][112];
    int t = threadIdx.x, lane = t & 31, wid = t >> 5;
    int wm = wid & 3, wn = wid >> 2;
    int x0 = blockIdx.x * 128, y = blockIdx.y, n = blockIdx.z;

    if (t < 112) {
        float bb = 0.f, sc = 0.f, sh = 0.f;
        if (t < 100) { bb = b2[t]; sc = g_bnp[200 + t]; sh = g_bnp[300 + t]; }
        sEp[0][t] = bb; sEp[1][t] = sc; sEp[2][t] = sh;
    }

    unsigned base0 = smem_u32(dsm);
    long pixbase = (long)n * PIX;
    const __nv_bfloat16* gh = (const __nv_bfloat16*)g_y1h4;
    const __nv_bfloat16* gl = (const __nv_bfloat16*)g_y1l4;

    // stage chunk ch into stage s (all 256 threads; 1560 cp.async of 16B)
    auto stage = [&](int ch, int s) {
        unsigned sb = base0 + s * C2_STG;
        for (int i = t; i < 1560; i += 256) {
            int half = i & 1, arr = (i >> 1) & 1, p = i >> 2;
            int r = p / 130, c = p - r * 130;
            int yy = y - 1 + r, xx = x0 - 1 + c;
            bool ok = ((unsigned)yy < 256u) && ((unsigned)xx < 256u);
            const __nv_bfloat16* g = arr ? gl : gh;
            long off = (pixbase + (long)yy * 256 + xx) * 112 + ch * 16 + half * 8;
            const void* src = ok ? (const void*)(g + off) : (const void*)g;
            unsigned dst = sb + arr * C2_AH + p * 32 + ((unsigned)((half ^ ((p >> 2) & 1))) << 4);
            unsigned sz = ok ? 16u : 0u;
            asm volatile("cp.async.cg.shared.global [%0], [%1], 16, %2;"
                         :: "r"(dst), "l"(src), "r"(sz));
        }
        asm volatile("cp.async.commit_group;" ::: "memory");
    };

    int arow = lane & 15;
    int akb  = (lane >> 4) & 1;

    float acc[2][7][4];
    #pragma unroll
    for (int s = 0; s < 2; s++)
        #pragma unroll
        for (int j = 0; j < 7; j++)
            #pragma unroll
            for (int e = 0; e < 4; e++) acc[s][j][e] = 0.f;

    stage(0, 0);

    for (int ch = 0; ch < 7; ch++) {
        asm volatile("cp.async.wait_group 0;" ::: "memory");
        __syncthreads();
        if (ch < 6) stage(ch + 1, (ch + 1) & 1);
        unsigned abase = base0 + (ch & 1) * C2_STG;
        const uint4* wb = g_WB + ch * 9 * 14 * 32;
        #pragma unroll
        for (int tg = 0; tg < 3; tg++) {
            #pragma unroll
            for (int dxi = 0; dxi < 3; dxi++) {
                unsigned ah[2][4], al[2][4];
                #pragma unroll
                for (int s2 = 0; s2 < 2; s2++) {
                    int pa = tg * 130 + wm * 32 + dxi + s2 * 16 + arow;
                    unsigned aoff = (unsigned)(pa * 32 + ((akb ^ ((pa >> 2) & 1)) << 4));
                    ldsm4(ah[s2], abase + aoff);
                    ldsm4(al[s2], abase + C2_AH + aoff);
                }
                const uint4* wt = wb + (tg * 3 + dxi) * 14 * 32 + lane;
                #pragma unroll
                for (int j = 0; j < 7; j++) {
                    uint4 w = __ldg(wt + (wn * 7 + j) * 32);
                    #pragma unroll
                    for (int s2 = 0; s2 < 2; s2++) {
                        mma16816(acc[s2][j], ah[s2], w.x, w.y);
                        mma16816(acc[s2][j], al[s2], w.x, w.y);
                        mma16816(acc[s2][j], ah[s2], w.z, w.w);
                    }
                }
            }
        }
    }

    // ---- epilogue: bias + relu + bn, write NCHW fp32 ----
    int rbase = wm * 32 + (lane >> 2);
    int ocl = (lane & 3) * 2;
    #pragma unroll
    for (int s = 0; s < 2; s++) {
        int pix0 = y * 256 + x0 + rbase + s * 16;
        #pragma unroll
        for (int j = 0; j < 7; j++) {
            int oc0 = (wn * 7 + j) * 8 + ocl;
            #pragma unroll
            for (int hh = 0; hh < 2; hh++) {
                int pp = pix0 + hh * 8;
                #pragma unroll
                for (int e = 0; e < 2; e++) {
                    int oc = oc0 + e;
                    if (oc < 100) {
                        float v = acc[s][j][hh * 2 + e];
                        v = fmaf(fmaxf(v + sEp[0][oc], 0.f), sEp[1][oc], sEp[2][oc]);
                        g_y2[(long)(n * CH + oc) * PIX + pp] = v;
                    }
                }
            }
        }
    }
}

// ---------------- conv3: 1x1, 100->32 + bn + argmax ----------------
__global__ void k_conv3(const float* __restrict__ W3, const float* __restrict__ b3,
                        float* __restrict__ out_mask) {
    __shared__ float w3s[100 * 32];
    __shared__ float p3[96];
    int t = threadIdx.x, n = blockIdx.y;
    for (int i = t; i < 3200; i += 256) {
        int oc = i & 31, c = i >> 5;
        w3s[i] = W3[oc * 100 + c];
    }
    if (t < 32) { p3[t] = b3[t]; p3[32 + t] = g_bnp[400 + t]; p3[64 + t] = g_bnp[432 + t]; }
    __syncthreads();
    int p = blockIdx.x * 256 + t;
    const float* yp = g_y2 + (long)n * CH * PIX + p;
    float acc[32];
    #pragma unroll
    for (int o = 0; o < 32; o++) acc[o] = 0.f;
    for (int c = 0; c < 100; c++) {
        float v = yp[c * PIX];
        #pragma unroll
        for (int o = 0; o < 32; o++) acc[o] = fmaf(v, w3s[c * 32 + o], acc[o]);
    }
    float best = -INFINITY;
    int bi = 0;
    #pragma unroll
    for (int o = 0; o < 32; o++) {
        float m = fmaf(acc[o] + p3[o], p3[32 + o], p3[64 + o]);
        out_mask[(long)(n * OD + o) * PIX + p] = m;
        if (m > best) { best = m; bi = o; }
    }
    g_lab[n * PIX + p] = bi;
}

// ---------------- segment stats ----------------
__global__ void k_zero() {
    int i = blockIdx.x * 256 + threadIdx.x;
    if (i < N_IMG * OD * NC) g_sums[i] = 0.f;
    if (i < N_IMG * OD) g_cnt[i] = 0.f;
}

__global__ void k_segsum() {
    __shared__ float sb[NC * OD];
    __shared__ float sc[OD];
    int t = threadIdx.x, n = blockIdx.y;
    for (int i = t; i < NC * OD; i += 256) sb[i] = 0.f;
    if (t < OD) sc[t] = 0.f;
    __syncthreads();
    int pbase = blockIdx.x * 4096;
    for (int it = 0; it < 16; it++) {
        int p = pbase + it * 256 + t;
        int l = g_lab[n * PIX + p];
        atomicAdd(&sc[l], 1.f);
        const float* fp = g_fup + (long)n * NC * PIX + p;
        #pragma unroll
        for (int c = 0; c < NC; c++) atomicAdd(&sb[c * OD + l], fp[c * PIX]);
    }
    __syncthreads();
    for (int i = t; i < NC * OD; i += 256) {
        int c = i / OD, l = i - c * OD;
        atomicAdd(&g_sums[(n * OD + l) * NC + c], sb[i]);
    }
    if (t < OD) atomicAdd(&g_cnt[n * OD + t], sc[t]);
}

__global__ void k_finish(float* __restrict__ cls_fea) {
    int t = threadIdx.x;
    float cnt = g_cnt[t];
    float inv = 1.f / fmaxf(cnt, 1.f);
    for (int c = 0; c < NC; c++) g_means[t * NC + c] = g_sums[t * NC + c] * inv;
    __syncthreads();
    if (t < N_IMG * NC) {
        int n = t / NC, c = t - n * NC;
        float m = -INFINITY;
        for (int s = 0; s < OD; s++)
            if (g_cnt[n * OD + s] > 0.f) m = fmaxf(m, g_means[(n * OD + s) * NC + c]);
        cls_fea[t] = m;
    }
}

__global__ void k_scatter(float* __restrict__ out_feat) {
    int idx = blockIdx.x * 256 + threadIdx.x;
    int p = idx & 65535;
    int nc = idx >> 16;
    int c = nc % NC, n = nc / NC;
    int l = g_lab[n * PIX + p];
    out_feat[idx] = g_means[(n * OD + l) * NC + c];
}

// ---------------- launch ----------------
extern "C" void kernel_launch(void* const* d_in, const int* in_sizes, int n_in,
                              void* d_out, int out_size) {
    const float* x   = (const float*)d_in[0];
    const float* x4  = (const float*)d_in[1];
    const float* Wc  = (const float*)d_in[2];
    const float* W1  = (const float*)d_in[3];
    const float* b1c = (const float*)d_in[4];
    const float* g1  = (const float*)d_in[5];
    const float* be1 = (const float*)d_in[6];
    const float* m1  = (const float*)d_in[7];
    const float* v1  = (const float*)d_in[8];
    const float* W2  = (const float*)d_in[9];
    const float* b2c = (const float*)d_in[10];
    const float* g2  = (const float*)d_in[11];
    const float* be2 = (const float*)d_in[12];
    const float* m2  = (const float*)d_in[13];
    const float* v2  = (const float*)d_in[14];
    const float* W3  = (const float*)d_in[15];
    const float* b3c = (const float*)d_in[16];
    const float* g3  = (const float*)d_in[17];
    const float* be3 = (const float*)d_in[18];
    const float* m3  = (const float*)d_in[19];
    const float* v3  = (const float*)d_in[20];

    float* out      = (float*)d_out;
    float* out_cls  = out;
    float* out_cfea = out + 160;
    float* out_feat = out + 320;
    float* out_mask = out + 320 + N_IMG*NC*PIX;

    cudaFuncSetAttribute(k_conv2m, cudaFuncAttributeMaxDynamicSharedMemorySize, C2_SMEM);

    k_bnprep<<<1, 256>>>(g1, be1, m1, v1, g2, be2, m2, v2, g3, be3, m3, v3);
    k_wprep<<<111, 256>>>(W2);
    k_classifier<<<N_IMG * NC, 256>>>(x4, Wc, out_cls);
    k_up<<<(N_IMG * NC * PIX) / 256, 256>>>();
    k_down<<<(N_IMG * 3 * PIX) / 256, 256>>>(x);
    k_conv1<<<dim3(PIX / 128, N_IMG), 128>>>(W1, b1c);
    k_conv2m<<<dim3(2, 256, N_IMG), 256, C2_SMEM>>>(b2c);
    k_conv3<<<dim3(PIX / 256, N_IMG), 256>>>(W3, b3c, out_mask);
    k_zero<<<21, 256>>>();
    k_segsum<<<dim3(16, N_IMG), 256>>>();
    k_finish<<<1, 256>>>(out_cfea);
    k_scatter<<<(N_IMG * NC * PIX) / 256, 256>>>(out_feat);
}

// round 5
// speedup vs baseline: 2.7283x; 1.1889x over previous
#include <cuda_runtime.h>
#include <cuda_bf16.h>
#include <math.h>

#define N_IMG 8
#define CH    100
#define OD    32
#define NC    20
#define HH    256
#define WW    256
#define PIX   (HH*WW)      // 65536

// ---------------- scratch (static device globals; no allocations) ----------------
__device__ float g_xs  [N_IMG*3*PIX];
__device__ float g_fs  [N_IMG*NC*256];
__device__ int   g_lab [N_IMG*PIX];
__device__ float g_sums[N_IMG*OD*NC];
__device__ float g_cnt [N_IMG*OD];
__device__ float g_means[N_IMG*OD*NC];
// bn params: [0,100)=s1 [100,200)=t1 [200,300)=s2 [300,400)=t2 [400,432)=s3 [432,464)=t3
__device__ float g_bnp[464];
// y1 in NHWC bf16 hi/lo, channel pitch 112 (channels >=100 zeroed). uint4-addressable.
__device__ uint4 g_y1h4[(size_t)N_IMG*PIX*14];
__device__ uint4 g_y1l4[(size_t)N_IMG*PIX*14];
// conv2 B fragments: [chunk 7][tap 9][tile 14][lane 32] uint4 = {bh0,bh1,bl0,bl1}
__device__ uint4 g_WB[7*9*14*32];

// ======== warp-mma helpers (family-safe PTX, sm_80+) ========
__device__ __forceinline__ unsigned smem_u32(const void* p) {
    unsigned a;
    asm("{ .reg .u64 t; cvta.to.shared.u64 t, %1; cvt.u32.u64 %0, t; }" : "=r"(a) : "l"(p));
    return a;
}
__device__ __forceinline__ void mma16816(float* d, const unsigned* a, unsigned b0, unsigned b1) {
    asm volatile("mma.sync.aligned.m16n8k16.row.col.f32.bf16.bf16.f32 "
        "{%0,%1,%2,%3}, {%4,%5,%6,%7}, {%8,%9}, {%0,%1,%2,%3};"
        : "+f"(d[0]), "+f"(d[1]), "+f"(d[2]), "+f"(d[3])
        : "r"(a[0]), "r"(a[1]), "r"(a[2]), "r"(a[3]), "r"(b0), "r"(b1));
}
__device__ __forceinline__ void ldsm4(unsigned* r, unsigned addr) {
    asm volatile("ldmatrix.sync.aligned.m8n8.x4.shared.b16 {%0,%1,%2,%3}, [%4];"
        : "=r"(r[0]), "=r"(r[1]), "=r"(r[2]), "=r"(r[3]) : "r"(addr));
}
__device__ __forceinline__ unsigned pk2(float a, float b) {
    unsigned lo = (unsigned)__bfloat16_as_ushort(__float2bfloat16(a));
    unsigned hi = (unsigned)__bfloat16_as_ushort(__float2bfloat16(b));
    return lo | (hi << 16);
}

// ---------------- bn prep ----------------
__global__ void k_bnprep(const float* g1, const float* be1, const float* m1, const float* v1,
                         const float* g2, const float* be2, const float* m2, const float* v2,
                         const float* g3, const float* be3, const float* m3, const float* v3) {
    int t = threadIdx.x;
    if (t < 100) {
        float s = g1[t] / sqrtf(v1[t] + 1e-5f);
        g_bnp[t] = s; g_bnp[100 + t] = be1[t] - m1[t] * s;
    } else if (t < 200) {
        int i = t - 100;
        float s = g2[i] / sqrtf(v2[i] + 1e-5f);
        g_bnp[200 + i] = s; g_bnp[300 + i] = be2[i] - m2[i] * s;
    } else if (t < 232) {
        int i = t - 200;
        float s = g3[i] / sqrtf(v3[i] + 1e-5f);
        g_bnp[400 + i] = s; g_bnp[432 + i] = be3[i] - m3[i] * s;
    }
}

// ---------------- conv2 weight prep: per-lane mma B fragments ----------------
__global__ void k_wprep(const float* __restrict__ W2) {
    int idx = blockIdx.x * 256 + threadIdx.x;   // 7*9*14*32 = 28224
    if (idx >= 28224) return;
    int l = idx & 31;
    int j = (idx >> 5) % 14;
    int tap = (idx / (32 * 14)) % 9;
    int c = idx / (32 * 14 * 9);
    int nn = j * 8 + (l >> 2);
    int k0 = (l & 3) * 2;
    float vh[4], vl[4];
    #pragma unroll
    for (int e = 0; e < 4; e++) {
        int k = k0 + (e & 1) + (e >> 1) * 8;   // k0, k0+1, k0+8, k0+9
        int ic = c * 16 + k;
        float v = 0.f;
        if (nn < 100 && ic < 100) v = W2[nn * 900 + ic * 9 + tap];
        float h = __bfloat162float(__float2bfloat16(v));
        vh[e] = h; vl[e] = v - h;
    }
    uint4 w;
    w.x = pk2(vh[0], vh[1]);
    w.y = pk2(vh[2], vh[3]);
    w.z = pk2(vl[0], vl[1]);
    w.w = pk2(vl[2], vl[3]);
    g_WB[idx] = w;
}

// ---------------- classifier 1x1 conv + spatial max ----------------
__global__ void k_classifier(const float* __restrict__ x4, const float* __restrict__ Wc,
                             float* __restrict__ cls_out) {
    int b = blockIdx.x;
    int n = b / NC, oc = b % NC;
    __shared__ float wsh[512];
    __shared__ float red[256];
    int t = threadIdx.x;
    wsh[t]       = Wc[oc * 512 + t];
    wsh[t + 256] = Wc[oc * 512 + t + 256];
    __syncthreads();
    const float* xp = x4 + (long)n * 512 * 256;
    float acc = 0.f;
    #pragma unroll 8
    for (int c = 0; c < 512; c++) acc = fmaf(xp[c * 256 + t], wsh[c], acc);
    g_fs[(n * NC + oc) * 256 + t] = acc;
    red[t] = acc; __syncthreads();
    for (int s = 128; s > 0; s >>= 1) {
        if (t < s) red[t] = fmaxf(red[t], red[t + s]);
        __syncthreads();
    }
    if (t == 0) cls_out[n * NC + oc] = red[0];
}

// ---------------- antialiased bilinear downsample 512 -> 256 ----------------
__device__ __forceinline__ float d_taps(int d, int* ix, float* wv) {
    float s = 0.f;
    #pragma unroll
    for (int i = 0; i < 4; i++) {
        int p = 2 * d - 1 + i;
        float w = (i == 0 || i == 3) ? 1.f : 3.f;
        if (p < 0 || p >= 512) { w = 0.f; p = p < 0 ? 0 : 511; }
        ix[i] = p; wv[i] = w; s += w;
    }
    return s;
}

__global__ void k_down(const float* __restrict__ x) {
    int idx = blockIdx.x * 256 + threadIdx.x;
    int xo = idx & 255;
    int yo = (idx >> 8) & 255;
    int nc = idx >> 16;
    int iy[4], ixs[4];
    float wy[4], wx[4];
    float ny = d_taps(yo, iy, wy);
    float nx = d_taps(xo, ixs, wx);
    const float* xp = x + (long)nc * 512 * 512;
    float acc = 0.f;
    #pragma unroll
    for (int i = 0; i < 4; i++) {
        const float* row = xp + iy[i] * 512;
        float r = wx[0]*row[ixs[0]] + wx[1]*row[ixs[1]] + wx[2]*row[ixs[2]] + wx[3]*row[ixs[3]];
        acc += wy[i] * r;
    }
    g_xs[idx] = acc / (ny * nx);
}

// ---------------- conv1: 3x3, 3->100, write NHWC bf16 hi/lo (pitch 112) ----------------
__global__ void k_conv1(const float* __restrict__ W1, const float* __restrict__ b1) {
    __shared__ float ws[2700];
    __shared__ float bs[100], ss[100], ts[100];
    int t = threadIdx.x, n = blockIdx.y;
    for (int i = t; i < 2700; i += 128) ws[i] = W1[i];
    if (t < 100) { bs[t] = b1[t]; ss[t] = g_bnp[t]; ts[t] = g_bnp[100 + t]; }
    __syncthreads();
    int p = blockIdx.x * 128 + t;
    int y = p >> 8, x = p & 255;
    const float* xp = g_xs + n * 3 * PIX;
    float in[27];
    int k = 0;
    #pragma unroll
    for (int c = 0; c < 3; c++)
        #pragma unroll
        for (int dy = -1; dy <= 1; dy++) {
            int yy = y + dy;
            #pragma unroll
            for (int dx = -1; dx <= 1; dx++) {
                int xx = x + dx;
                in[k++] = ((unsigned)yy < 256u && (unsigned)xx < 256u) ? xp[c * PIX + yy * 256 + xx] : 0.f;
            }
        }
    long obase = ((long)n * PIX + p) * 14;
    for (int oc0 = 0; oc0 < 112; oc0 += 8) {
        unsigned hw[4], lw[4];
        #pragma unroll
        for (int e2 = 0; e2 < 4; e2++) {
            float v[2];
            #pragma unroll
            for (int u = 0; u < 2; u++) {
                int oc = oc0 + e2 * 2 + u;
                float a = 0.f;
                if (oc < 100) {
                    a = bs[oc];
                    const float* w = ws + oc * 27;
                    #pragma unroll
                    for (int j = 0; j < 27; j++) a = fmaf(in[j], w[j], a);
                    a = fmaxf(a, 0.f);
                    a = fmaf(a, ss[oc], ts[oc]);
                }
                v[u] = a;
            }
            float h0 = __bfloat162float(__float2bfloat16(v[0]));
            float h1 = __bfloat162float(__float2bfloat16(v[1]));
            hw[e2] = pk2(v[0], v[1]);
            lw[e2] = pk2(v[0] - h0, v[1] - h1);
        }
        g_y1h4[obase + (oc0 >> 3)] = make_uint4(hw[0], hw[1], hw[2], hw[3]);
        g_y1l4[obase + (oc0 >> 3)] = make_uint4(lw[0], lw[1], lw[2], lw[3]);
    }
}

// ---------------- conv2 + conv3 fused: mma implicit GEMM, then 1x1+bn+argmax ----------
// CTA tile: M=128 pixels x N=112 oc; K = 7 chunks x 16 ic; 9 taps as shifted GEMMs.
// dynamic smem: max(2 stages x 24960 A, sY 128x114 fp32) = 58368 bytes
#define C2_AH    12480
#define C2_STG   24960
#define C2_SMEM  58368

__global__ __launch_bounds__(256, 2) void k_conv2m(const float* __restrict__ b2,
                                                   const float* __restrict__ W3,
                                                   const float* __restrict__ b3,
                                                   float* __restrict__ out_mask) {
    extern __shared__ __align__(16) unsigned char dsm[];
    __shared__ float sEp[3][112];
    __shared__ float4 w3s4[800];   // [c][q] -> oc 4q..4q+3
    __shared__ float p3[96];
    int t = threadIdx.x, lane = t & 31, wid = t >> 5;
    int wm = wid & 3, wn = wid >> 2;
    int x0 = blockIdx.x * 128, y = blockIdx.y, n = blockIdx.z;

    if (t < 112) {
        float bb = 0.f, sc = 0.f, sh = 0.f;
        if (t < 100) { bb = b2[t]; sc = g_bnp[200 + t]; sh = g_bnp[300 + t]; }
        sEp[0][t] = bb; sEp[1][t] = sc; sEp[2][t] = sh;
    }
    for (int i = t; i < 800; i += 256) {
        int q = i & 7, c = i >> 3;
        w3s4[i] = make_float4(W3[(4*q+0)*100 + c], W3[(4*q+1)*100 + c],
                              W3[(4*q+2)*100 + c], W3[(4*q+3)*100 + c]);
    }
    if (t < 32) { p3[t] = b3[t]; p3[32 + t] = g_bnp[400 + t]; p3[64 + t] = g_bnp[432 + t]; }

    unsigned base0 = smem_u32(dsm);
    long pixbase = (long)n * PIX;
    const __nv_bfloat16* gh = (const __nv_bfloat16*)g_y1h4;
    const __nv_bfloat16* gl = (const __nv_bfloat16*)g_y1l4;

    auto stage = [&](int ch, int s) {
        unsigned sb = base0 + s * C2_STG;
        for (int i = t; i < 1560; i += 256) {
            int half = i & 1, arr = (i >> 1) & 1, p = i >> 2;
            int r = p / 130, c = p - r * 130;
            int yy = y - 1 + r, xx = x0 - 1 + c;
            bool ok = ((unsigned)yy < 256u) && ((unsigned)xx < 256u);
            const __nv_bfloat16* g = arr ? gl : gh;
            long off = (pixbase + (long)yy * 256 + xx) * 112 + ch * 16 + half * 8;
            const void* src = ok ? (const void*)(g + off) : (const void*)g;
            unsigned dst = sb + arr * C2_AH + p * 32 + ((unsigned)((half ^ ((p >> 2) & 1))) << 4);
            unsigned sz = ok ? 16u : 0u;
            asm volatile("cp.async.cg.shared.global [%0], [%1], 16, %2;"
                         :: "r"(dst), "l"(src), "r"(sz));
        }
        asm volatile("cp.async.commit_group;" ::: "memory");
    };

    int arow = lane & 15;
    int akb  = (lane >> 4) & 1;

    float acc[2][7][4];
    #pragma unroll
    for (int s = 0; s < 2; s++)
        #pragma unroll
        for (int j = 0; j < 7; j++)
            #pragma unroll
            for (int e = 0; e < 4; e++) acc[s][j][e] = 0.f;

    stage(0, 0);

    for (int ch = 0; ch < 7; ch++) {
        asm volatile("cp.async.wait_group 0;" ::: "memory");
        __syncthreads();
        if (ch < 6) stage(ch + 1, (ch + 1) & 1);
        unsigned abase = base0 + (ch & 1) * C2_STG;
        const uint4* wb = g_WB + ch * 9 * 14 * 32;
        #pragma unroll
        for (int tap = 0; tap < 9; tap++) {
            int tg = tap / 3, dxi = tap - tg * 3;
            // batched B-fragment loads (MLP=7, L2-hot)
            uint4 w[7];
            const uint4* wt = wb + tap * 448 + (wn * 7) * 32 + lane;
            #pragma unroll
            for (int j = 0; j < 7; j++) w[j] = __ldg(wt + j * 32);
            unsigned ah[2][4], al[2][4];
            #pragma unroll
            for (int s2 = 0; s2 < 2; s2++) {
                int pa = tg * 130 + wm * 32 + dxi + s2 * 16 + arow;
                unsigned aoff = (unsigned)(pa * 32 + ((akb ^ ((pa >> 2) & 1)) << 4));
                ldsm4(ah[s2], abase + aoff);
                ldsm4(al[s2], abase + C2_AH + aoff);
            }
            #pragma unroll
            for (int j = 0; j < 7; j++) {
                #pragma unroll
                for (int s2 = 0; s2 < 2; s2++) {
                    mma16816(acc[s2][j], ah[s2], w[j].x, w[j].y);
                    mma16816(acc[s2][j], al[s2], w[j].x, w[j].y);
                    mma16816(acc[s2][j], ah[s2], w[j].z, w[j].w);
                }
            }
        }
    }

    // ---- epilogue phase 1: bias + relu + bn -> sY[128][114] ----
    __syncthreads();   // all ldsm reads of A done; reuse dsm as sY
    float* sY = (float*)dsm;
    int rbase = wm * 32 + (lane >> 2);
    int ocl = (lane & 3) * 2;
    #pragma unroll
    for (int s = 0; s < 2; s++) {
        #pragma unroll
        for (int j = 0; j < 7; j++) {
            int oc0 = (wn * 7 + j) * 8 + ocl;
            float b = sEp[0][oc0],     sc = sEp[1][oc0],     sh = sEp[2][oc0];
            float b1 = sEp[0][oc0+1],  sc1 = sEp[1][oc0+1],  sh1 = sEp[2][oc0+1];
            #pragma unroll
            for (int hh = 0; hh < 2; hh++) {
                int m = rbase + s * 16 + hh * 8;
                float v0 = fmaf(fmaxf(acc[s][j][hh*2+0] + b,  0.f), sc,  sh);
                float v1 = fmaf(fmaxf(acc[s][j][hh*2+1] + b1, 0.f), sc1, sh1);
                *(float2*)(sY + m * 114 + oc0) = make_float2(v0, v1);
            }
        }
    }
    __syncthreads();

    // ---- epilogue phase 2: conv3 1x1 (100->32) + bn + argmax ----
    {
        int p_loc = t >> 1, grp = t & 1;
        const float* yrow = sY + p_loc * 114;
        float a3[16];
        #pragma unroll
        for (int i = 0; i < 16; i++) a3[i] = 0.f;
        const float4* wq = w3s4 + grp * 4;
        #pragma unroll 4
        for (int c = 0; c < 100; c++) {
            float v = yrow[c];
            float4 w0 = wq[c*8+0], w1 = wq[c*8+1], w2 = wq[c*8+2], w3f = wq[c*8+3];
            a3[0]  = fmaf(v, w0.x, a3[0]);  a3[1]  = fmaf(v, w0.y, a3[1]);
            a3[2]  = fmaf(v, w0.z, a3[2]);  a3[3]  = fmaf(v, w0.w, a3[3]);
            a3[4]  = fmaf(v, w1.x, a3[4]);  a3[5]  = fmaf(v, w1.y, a3[5]);
            a3[6]  = fmaf(v, w1.z, a3[6]);  a3[7]  = fmaf(v, w1.w, a3[7]);
            a3[8]  = fmaf(v, w2.x, a3[8]);  a3[9]  = fmaf(v, w2.y, a3[9]);
            a3[10] = fmaf(v, w2.z, a3[10]); a3[11] = fmaf(v, w2.w, a3[11]);
            a3[12] = fmaf(v, w3f.x, a3[12]); a3[13] = fmaf(v, w3f.y, a3[13]);
            a3[14] = fmaf(v, w3f.z, a3[14]); a3[15] = fmaf(v, w3f.w, a3[15]);
        }
        int pix = y * 256 + x0 + p_loc;
        float best = -INFINITY; int bi = 0;
        #pragma unroll
        for (int i = 0; i < 16; i++) {
            int oc = grp * 16 + i;
            float m = fmaf(a3[i] + p3[oc], p3[32 + oc], p3[64 + oc]);
            out_mask[(long)(n * OD + oc) * PIX + pix] = m;
            if (m > best) { best = m; bi = oc; }
        }
        float obest = __shfl_xor_sync(0xffffffffu, best, 1);
        int   obi   = __shfl_xor_sync(0xffffffffu, bi, 1);
        // strict first-occurrence: lower oc wins ties; grp0 holds lower range
        if (grp == 0) { if (obest > best) { best = obest; bi = obi; } }
        else          { if (obest >= best) { best = obest; bi = obi; } }
        if (grp == 0) g_lab[n * PIX + pix] = bi;
    }
}

// ---------------- segment stats (bilinear upsample inlined) ----------------
__global__ void k_zero() {
    int i = blockIdx.x * 256 + threadIdx.x;
    if (i < N_IMG * OD * NC) g_sums[i] = 0.f;
    if (i < N_IMG * OD) g_cnt[i] = 0.f;
}

__global__ void k_segsum() {
    __shared__ float sb[NC * OD];
    __shared__ float sc[OD];
    __shared__ float sfs[NC * 256];
    int t = threadIdx.x, n = blockIdx.y;
    for (int i = t; i < NC * OD; i += 256) sb[i] = 0.f;
    if (t < OD) sc[t] = 0.f;
    for (int i = t; i < NC * 256; i += 256) sfs[i] = g_fs[n * NC * 256 + i];
    __syncthreads();
    int pbase = blockIdx.x * 4096;
    for (int it = 0; it < 16; it++) {
        int p = pbase + it * 256 + t;
        int l = g_lab[n * PIX + p];
        atomicAdd(&sc[l], 1.f);
        int x = p & 255, y = p >> 8;
        float sy = (y + 0.5f) * 0.0625f - 0.5f;
        float sx = (x + 0.5f) * 0.0625f - 0.5f;
        float fy0 = floorf(sy), fx0 = floorf(sx);
        float fy = sy - fy0, fx = sx - fx0;
        int y0 = max((int)fy0, 0), y1 = min((int)fy0 + 1, 15);
        int x0 = max((int)fx0, 0), x1 = min((int)fx0 + 1, 15);
        #pragma unroll 4
        for (int c = 0; c < NC; c++) {
            const float* fs = sfs + c * 256;
            float v00 = fs[y0 * 16 + x0], v01 = fs[y0 * 16 + x1];
            float v10 = fs[y1 * 16 + x0], v11 = fs[y1 * 16 + x1];
            float v = (v00 * (1.f - fx) + v01 * fx) * (1.f - fy)
                    + (v10 * (1.f - fx) + v11 * fx) * fy;
            atomicAdd(&sb[c * OD + l], v);
        }
    }
    __syncthreads();
    for (int i = t; i < NC * OD; i += 256) {
        int c = i / OD, l = i - c * OD;
        atomicAdd(&g_sums[(n * OD + l) * NC + c], sb[i]);
    }
    if (t < OD) atomicAdd(&g_cnt[n * OD + t], sc[t]);
}

__global__ void k_finish(float* __restrict__ cls_fea) {
    int t = threadIdx.x;
    float cnt = g_cnt[t];
    float inv = 1.f / fmaxf(cnt, 1.f);
    for (int c = 0; c < NC; c++) g_means[t * NC + c] = g_sums[t * NC + c] * inv;
    __syncthreads();
    if (t < N_IMG * NC) {
        int n = t / NC, c = t - n * NC;
        float m = -INFINITY;
        for (int s = 0; s < OD; s++)
            if (g_cnt[n * OD + s] > 0.f) m = fmaxf(m, g_means[(n * OD + s) * NC + c]);
        cls_fea[t] = m;
    }
}

__global__ void k_scatter(float* __restrict__ out_feat) {
    int idx = blockIdx.x * 256 + threadIdx.x;
    int p = idx & 65535;
    int nc = idx >> 16;
    int c = nc % NC, n = nc / NC;
    int l = g_lab[n * PIX + p];
    out_feat[idx] = g_means[(n * OD + l) * NC + c];
}

// ---------------- launch ----------------
extern "C" void kernel_launch(void* const* d_in, const int* in_sizes, int n_in,
                              void* d_out, int out_size) {
    const float* x   = (const float*)d_in[0];
    const float* x4  = (const float*)d_in[1];
    const float* Wc  = (const float*)d_in[2];
    const float* W1  = (const float*)d_in[3];
    const float* b1c = (const float*)d_in[4];
    const float* g1  = (const float*)d_in[5];
    const float* be1 = (const float*)d_in[6];
    const float* m1  = (const float*)d_in[7];
    const float* v1  = (const float*)d_in[8];
    const float* W2  = (const float*)d_in[9];
    const float* b2c = (const float*)d_in[10];
    const float* g2  = (const float*)d_in[11];
    const float* be2 = (const float*)d_in[12];
    const float* m2  = (const float*)d_in[13];
    const float* v2  = (const float*)d_in[14];
    const float* W3  = (const float*)d_in[15];
    const float* b3c = (const float*)d_in[16];
    const float* g3  = (const float*)d_in[17];
    const float* be3 = (const float*)d_in[18];
    const float* m3  = (const float*)d_in[19];
    const float* v3  = (const float*)d_in[20];

    float* out      = (float*)d_out;
    float* out_cls  = out;
    float* out_cfea = out + 160;
    float* out_feat = out + 320;
    float* out_mask = out + 320 + N_IMG*NC*PIX;

    cudaFuncSetAttribute(k_conv2m, cudaFuncAttributeMaxDynamicSharedMemorySize, C2_SMEM);

    k_bnprep<<<1, 256>>>(g1, be1, m1, v1, g2, be2, m2, v2, g3, be3, m3, v3);
    k_wprep<<<111, 256>>>(W2);
    k_classifier<<<N_IMG * NC, 256>>>(x4, Wc, out_cls);
    k_down<<<(N_IMG * 3 * PIX) / 256, 256>>>(x);
    k_conv1<<<dim3(PIX / 128, N_IMG), 128>>>(W1, b1c);
    k_conv2m<<<dim3(2, 256, N_IMG), 256, C2_SMEM>>>(b2c, W3, b3c, out_mask);
    k_zero<<<21, 256>>>();
    k_segsum<<<dim3(16, N_IMG), 256>>>();
    k_finish<<<1, 256>>>(out_cfea);
    k_scatter<<<(N_IMG * NC * PIX) / 256, 256>>>(out_feat);
}